// round 13
// baseline (speedup 1.0000x reference)
#include <cuda_runtime.h>
#include <cuda_bf16.h>
#include <cstdint>

#define S_DIM 128
#define N_DIM 256
#define CM    256
#define CH    32
#define CZ    128
#define KCD   (CH*CH)            // 1024
#define MPAIRS (N_DIM*N_DIM)     // 65536
#define NC    (N_DIM*CH)         // 8192

// ---------------- device scratch ------------------------------------------
__device__ __align__(16) unsigned short g_ah[S_DIM * NC];  // a hi bf16 [s][n*32+c]
__device__ __align__(16) unsigned short g_al[S_DIM * NC];  // a lo
__device__ __align__(16) unsigned short g_bh[S_DIM * NC];  // b hi
__device__ __align__(16) unsigned short g_bl[S_DIM * NC];  // b lo
__device__ __align__(16) unsigned short g_qh[(size_t)NC * NC]; // Q hi bf16 [i*32+c][j*32+d]
__device__ __align__(16) unsigned short g_ql[(size_t)NC * NC]; // Q lo bf16
__device__ __align__(16) unsigned short g_wth[CZ * KCD]; // woT hi bf16 [z][cd]
__device__ __align__(16) unsigned short g_wtl[CZ * KCD]; // woT lo bf16
__device__ float g_norm[MPAIRS];                         // norm + eps

// ---------------- helpers ---------------------------------------------------
__device__ __forceinline__ uint32_t smem_u32(const void* p) {
    uint32_t a;
    asm("{ .reg .u64 t; cvta.to.shared.u64 t, %1; cvt.u32.u64 %0, t; }"
        : "=r"(a) : "l"(p));
    return a;
}
__device__ __forceinline__ void split_bf16(float v, unsigned short& h, unsigned short& l) {
    __nv_bfloat16 hb = __float2bfloat16(v);
    __nv_bfloat16 lb = __float2bfloat16(v - __bfloat162float(hb));
    h = __bfloat16_as_ushort(hb);
    l = __bfloat16_as_ushort(lb);
}
__device__ __forceinline__ void ldsm_x4(uint32_t* r, uint32_t a) {
    asm volatile("ldmatrix.sync.aligned.m8n8.x4.shared.b16 {%0,%1,%2,%3}, [%4];"
        : "=r"(r[0]), "=r"(r[1]), "=r"(r[2]), "=r"(r[3]) : "r"(a));
}
__device__ __forceinline__ void ldsm_x4_t(uint32_t* r, uint32_t a) {
    asm volatile("ldmatrix.sync.aligned.m8n8.x4.trans.shared.b16 {%0,%1,%2,%3}, [%4];"
        : "=r"(r[0]), "=r"(r[1]), "=r"(r[2]), "=r"(r[3]) : "r"(a));
}
__device__ __forceinline__ void mma16816(float* c, const uint32_t* a, const uint32_t* b) {
    asm volatile("mma.sync.aligned.m16n8k16.row.col.f32.bf16.bf16.f32 "
        "{%0,%1,%2,%3}, {%4,%5,%6,%7}, {%8,%9}, {%0,%1,%2,%3};"
        : "+f"(c[0]), "+f"(c[1]), "+f"(c[2]), "+f"(c[3])
        : "r"(a[0]), "r"(a[1]), "r"(a[2]), "r"(a[3]), "r"(b[0]), "r"(b[1]));
}
#define CP_ASYNC16(dst, src) \
    asm volatile("cp.async.cg.shared.global [%0], [%1], 16;" \
                 :: "r"(dst), "l"(src) : "memory")
#define CP_COMMIT()  asm volatile("cp.async.commit_group;" ::: "memory")
#define CP_WAIT(n)   asm volatile("cp.async.wait_group %0;" :: "n"(n) : "memory")

// ---------------------------------------------------------------------------
// Kernel A: LayerNorm + two projections + hi/lo bf16 split (proven)
// ---------------------------------------------------------------------------
__global__ void __launch_bounds__(256) ln_proj_kernel(
    const float* __restrict__ m, const float* __restrict__ mask,
    const float* __restrict__ ln_w, const float* __restrict__ ln_b,
    const float* __restrict__ w1, const float* __restrict__ b1,
    const float* __restrict__ w2, const float* __restrict__ b2)
{
    __shared__ float lnsm[8][CM];
    __shared__ float pa[4][8][CH];
    __shared__ float pb[4][8][CH];
    __shared__ float masksm[8];

    int t = threadIdx.x, warp = t >> 5, lane = t & 31;
    int bid = blockIdx.x;
    int s = bid >> 5, n0 = (bid & 31) << 3;

    {
        int r = warp;
        const float* row = m + ((size_t)s * N_DIM + n0 + r) * CM;
        float v[8], sum = 0.f, sq = 0.f;
#pragma unroll
        for (int x = 0; x < 8; x++) { v[x] = row[lane + 32 * x]; sum += v[x]; sq += v[x] * v[x]; }
#pragma unroll
        for (int o = 16; o > 0; o >>= 1) {
            sum += __shfl_xor_sync(0xffffffffu, sum, o);
            sq  += __shfl_xor_sync(0xffffffffu, sq, o);
        }
        float mu = sum * (1.f / CM);
        float inv = rsqrtf(sq * (1.f / CM) - mu * mu + 1e-5f);
#pragma unroll
        for (int x = 0; x < 8; x++) {
            int k = lane + 32 * x;
            lnsm[r][k] = (v[x] - mu) * inv * ln_w[k] + ln_b[k];
        }
        if (lane == 0) masksm[r] = mask[s * N_DIM + n0 + r];
    }
    __syncthreads();
    {
        const float* W = (warp < 4) ? w1 : w2;
        int wq = warp & 3;
        float acc[8];
#pragma unroll
        for (int r = 0; r < 8; r++) acc[r] = 0.f;
        int kbeg = wq * 64;
#pragma unroll 8
        for (int k = kbeg; k < kbeg + 64; k++) {
            float wv = W[k * CH + lane];
#pragma unroll
            for (int r = 0; r < 8; r++) acc[r] += lnsm[r][k] * wv;
        }
        if (warp < 4) {
#pragma unroll
            for (int r = 0; r < 8; r++) pa[wq][r][lane] = acc[r];
        } else {
#pragma unroll
            for (int r = 0; r < 8; r++) pb[wq][r][lane] = acc[r];
        }
    }
    __syncthreads();
    {
        int r = t >> 5, c = t & 31;
        float av = pa[0][r][c] + pa[1][r][c] + pa[2][r][c] + pa[3][r][c] + b1[c];
        float bv = pb[0][r][c] + pb[1][r][c] + pb[2][r][c] + pb[3][r][c] + b2[c];
        float mv = masksm[r];
        size_t off = ((size_t)s * N_DIM + n0 + r) * CH + c;
        unsigned short h, l;
        split_bf16(av * mv, h, l);
        g_ah[off] = h;  g_al[off] = l;
        split_bf16(bv * mv, h, l);
        g_bh[off] = h;  g_bl[off] = l;
    }
}

// woT: transpose + hi/lo split of wo  ([cd][z] -> [z][cd])
__global__ void __launch_bounds__(256) wot_kernel(const float* __restrict__ wo)
{
    int idx = blockIdx.x * 256 + threadIdx.x;
    int z = idx >> 10, cd = idx & 1023;
    unsigned short h, l;
    split_bf16(wo[cd * CZ + z], h, l);
    g_wth[z * KCD + cd] = h;
    g_wtl[z * KCD + cd] = l;
}

// norm[i,j] = sum_s mask[s,i]*mask[s,j] + eps
__global__ void __launch_bounds__(256) norm_kernel(const float* __restrict__ mask)
{
    int i = blockIdx.x, j = threadIdx.x;
    float acc = 0.f;
#pragma unroll 8
    for (int s = 0; s < S_DIM; s++)
        acc += mask[s * N_DIM + i] * mask[s * N_DIM + j];
    g_norm[i * N_DIM + j] = acc + 1e-3f;
}

// ---------------------------------------------------------------------------
// GEMM1: Q = a^T b  (8192x8192, K=128), 3-pass bf16 mma.  (proven round 12)
// 512 threads, warp tile 32x32, pure cp.async fill, double-buffered.
// ---------------------------------------------------------------------------
#define LDM1   136
#define LDM1B  (LDM1*2)          // 272
#define PL1    (64 * LDM1B)      // 17408 per plane
#define STG1   (4 * PL1)         // 69632 per stage
#define SM1    (2 * STG1)        // 139264

__device__ __forceinline__ void g1_fill(int ch, int sg, int t, int m0, int n0,
                                        uint32_t sb)
{
#pragma unroll
    for (int it = 0; it < 2; it++) {
        int vi = it * 512 + t;                  // 0..1023 chunks per plane
        int sl = vi >> 4, q = vi & 15;
        size_t sra = (size_t)(ch * 64 + sl) * NC + m0 + q * 8;
        size_t srb = (size_t)(ch * 64 + sl) * NC + n0 + q * 8;
        uint32_t dst = sb + (uint32_t)sg * STG1 + (uint32_t)(sl * LDM1B + q * 16);
        CP_ASYNC16(dst,            g_ah + sra);
        CP_ASYNC16(dst + PL1,      g_al + sra);
        CP_ASYNC16(dst + 2 * PL1,  g_bh + srb);
        CP_ASYNC16(dst + 3 * PL1,  g_bl + srb);
    }
}

__global__ void __launch_bounds__(512) gemm1_kernel()
{
    extern __shared__ unsigned char sm1[];
    const uint32_t sb = smem_u32(sm1);

    int t = threadIdx.x, w = t >> 5, lane = t & 31;
    int wm = w >> 2, wn = w & 3;                // 4x4 warps, tile 32x32
    int m0 = blockIdx.x * 128, n0 = blockIdx.y * 128;

    float C[2][4][4];
#pragma unroll
    for (int mi = 0; mi < 2; mi++)
#pragma unroll
        for (int ni = 0; ni < 4; ni++)
#pragma unroll
            for (int e = 0; e < 4; e++) C[mi][ni][e] = 0.f;

    g1_fill(0, 0, t, m0, n0, sb);
    CP_COMMIT();
    g1_fill(1, 1, t, m0, n0, sb);
    CP_COMMIT();

    for (int ch = 0; ch < 2; ch++) {
        if (ch == 0) { CP_WAIT(1); } else { CP_WAIT(0); }
        __syncthreads();

        uint32_t Sb = sb + (uint32_t)(ch & 1) * STG1;
#pragma unroll
        for (int pass = 0; pass < 3; pass++) {
            uint32_t Ab = Sb + ((pass == 2) ? PL1 : 0);
            uint32_t Bb = Sb + 2 * PL1 + ((pass == 1) ? PL1 : 0);
#pragma unroll
            for (int ks = 0; ks < 4; ks++) {
                int kb = ks * 16;
                uint32_t af[2][4];
#pragma unroll
                for (int mi = 0; mi < 2; mi++) {
                    int mb = wm * 32 + mi * 16;
                    uint32_t addr = Ab
                        + (uint32_t)(kb + ((lane >> 4) & 1) * 8 + (lane & 7)) * LDM1B
                        + (uint32_t)(mb + (lane & 8)) * 2;
                    ldsm_x4_t(af[mi], addr);
                }
                uint32_t bf[4][2];
#pragma unroll
                for (int np = 0; np < 2; np++) {
                    int nb = wn * 32 + np * 16;
                    uint32_t addr = Bb
                        + (uint32_t)(kb + ((lane >> 3) & 1) * 8 + (lane & 7)) * LDM1B
                        + (uint32_t)(nb + (lane >> 4) * 8) * 2;
                    uint32_t r4[4];
                    ldsm_x4_t(r4, addr);
                    bf[2 * np][0] = r4[0]; bf[2 * np][1] = r4[1];
                    bf[2 * np + 1][0] = r4[2]; bf[2 * np + 1][1] = r4[3];
                }
#pragma unroll
                for (int mi = 0; mi < 2; mi++)
#pragma unroll
                    for (int ni = 0; ni < 4; ni++)
                        mma16816(C[mi][ni], af[mi], bf[ni]);
            }
        }
    }

    // ---- epilogue: stage C (hi/lo) in stage-0 smem, then coalesced STG ----
    {
        unsigned short* Eh = (unsigned short*)(sm1);            // [128][136]
        unsigned short* El = (unsigned short*)(sm1 + 2 * PL1);  // [128][136]
        int gid = lane >> 2, ctid = lane & 3;
#pragma unroll
        for (int mi = 0; mi < 2; mi++) {
#pragma unroll
            for (int rr = 0; rr < 2; rr++) {
                int r = wm * 32 + mi * 16 + gid + rr * 8;
#pragma unroll
                for (int ni = 0; ni < 4; ni++) {
                    int col = wn * 32 + ni * 8 + 2 * ctid;
                    unsigned short h0, l0, h1, l1;
                    split_bf16(C[mi][ni][rr * 2 + 0], h0, l0);
                    split_bf16(C[mi][ni][rr * 2 + 1], h1, l1);
                    *(uint32_t*)(Eh + r * LDM1 + col) = ((uint32_t)h1 << 16) | h0;
                    *(uint32_t*)(El + r * LDM1 + col) = ((uint32_t)l1 << 16) | l0;
                }
            }
        }
        __syncthreads();
#pragma unroll
        for (int it = 0; it < 4; it++) {
            int vi = it * 512 + t;                   // 0..2047
            int r = vi >> 4, q = vi & 15;
            uint4 vh = *(const uint4*)(sm1 + (uint32_t)(r * LDM1B + q * 16));
            uint4 vl = *(const uint4*)(sm1 + 2 * PL1 + (uint32_t)(r * LDM1B + q * 16));
            size_t dst = (size_t)(m0 + r) * NC + n0 + q * 8;
            *(uint4*)(g_qh + dst) = vh;
            *(uint4*)(g_ql + dst) = vl;
        }
    }
}

// ---------------------------------------------------------------------------
// GEMM2: out = Q @ woT  (M=65536, N=128, K=1024), 3-pass, double-buffered.
// NEW: 512 threads, 4x4 warp grid, 32x32 warp tile (mirror of gemm1's fix).
// ---------------------------------------------------------------------------
#define LDK2   72
#define LDK2B  (LDK2*2)          // 144
#define APL    (128 * LDK2B)     // 18432
#define ASTG   (2 * APL)         // 36864 per stage
#define OFF_W  (2 * ASTG)        // 73728
#define SM2    (OFF_W + 2 * ASTG) // 147456

__device__ __forceinline__ void g2_fill_a(int ch, int sg, int t, int i32, int j0,
                                          uint32_t sb)
{
#pragma unroll
    for (int it = 0; it < 2; it++) {
        int vi = it * 512 + t;                  // 0..1023
        int cl = vi >> 9, rem = vi & 511;
        int jl = rem >> 2, q = rem & 3;
        size_t src = (size_t)(i32 + 2 * ch + cl) * NC + (size_t)(j0 + jl) * 32 + q * 8;
        uint32_t dst = sb + (uint32_t)sg * ASTG + (uint32_t)(jl * LDK2B + cl * 64 + q * 16);
        CP_ASYNC16(dst, g_qh + src);
        CP_ASYNC16(dst + APL, g_ql + src);
    }
}
__device__ __forceinline__ void g2_fill_w(int ch, int sg, int t, uint32_t sb)
{
#pragma unroll
    for (int it = 0; it < 2; it++) {
        int vi = it * 512 + t;                  // 0..1023
        int r = vi >> 3, q = vi & 7;
        size_t src = (size_t)r * KCD + ch * 64 + q * 8;
        uint32_t dst = sb + OFF_W + (uint32_t)sg * ASTG + (uint32_t)(r * LDK2B + q * 16);
        CP_ASYNC16(dst, g_wth + src);
        CP_ASYNC16(dst + APL, g_wtl + src);
    }
}

__global__ void __launch_bounds__(512) gemm2_kernel(
    const float* __restrict__ bo, float* __restrict__ out)
{
    extern __shared__ unsigned char sm2[];
    const uint32_t sb = smem_u32(sm2);

    int t = threadIdx.x, w = t >> 5, lane = t & 31;
    int wm = w >> 2, wn = w & 3;                // 4x4 warps, tile 32x32
    int i = blockIdx.x >> 1;
    int j0 = (blockIdx.x & 1) * 128;
    int i32 = i * 32;

    float C[2][4][4];
#pragma unroll
    for (int mi = 0; mi < 2; mi++)
#pragma unroll
        for (int ni = 0; ni < 4; ni++)
#pragma unroll
            for (int e = 0; e < 4; e++) C[mi][ni][e] = 0.f;

    g2_fill_a(0, 0, t, i32, j0, sb);
    g2_fill_w(0, 0, t, sb);
    CP_COMMIT();
    g2_fill_a(1, 1, t, i32, j0, sb);
    g2_fill_w(1, 1, t, sb);
    CP_COMMIT();

    for (int ch = 0; ch < 16; ch++) {
        if (ch < 15) { CP_WAIT(1); } else { CP_WAIT(0); }
        __syncthreads();

        uint32_t Abase = sb + (uint32_t)(ch & 1) * ASTG;
        uint32_t Wbase = sb + OFF_W + (uint32_t)(ch & 1) * ASTG;
#pragma unroll
        for (int pass = 0; pass < 3; pass++) {
            uint32_t Ab = Abase + ((pass == 2) ? APL : 0);
            uint32_t Bb = Wbase + ((pass == 1) ? APL : 0);
#pragma unroll
            for (int ks = 0; ks < 4; ks++) {
                int kb = ks * 16;
                uint32_t af[2][4];
#pragma unroll
                for (int mi = 0; mi < 2; mi++) {
                    int mb = wm * 32 + mi * 16;
                    uint32_t addr = Ab
                        + (uint32_t)(mb + (lane & 15)) * LDK2B
                        + (uint32_t)(kb + (lane >> 4) * 8) * 2;
                    ldsm_x4(af[mi], addr);
                }
                uint32_t bf[4][2];
#pragma unroll
                for (int np = 0; np < 2; np++) {
                    int nb = wn * 32 + np * 16;
                    uint32_t addr = Bb
                        + (uint32_t)(nb + (lane >> 4) * 8 + (lane & 7)) * LDK2B
                        + (uint32_t)(kb + ((lane >> 3) & 1) * 8) * 2;
                    uint32_t r4[4];
                    ldsm_x4(r4, addr);
                    bf[2 * np][0] = r4[0]; bf[2 * np][1] = r4[1];
                    bf[2 * np + 1][0] = r4[2]; bf[2 * np + 1][1] = r4[3];
                }
#pragma unroll
                for (int mi = 0; mi < 2; mi++)
#pragma unroll
                    for (int ni = 0; ni < 4; ni++)
                        mma16816(C[mi][ni], af[mi], bf[ni]);
            }
        }
        __syncthreads();
        if (ch + 2 < 16) {
            g2_fill_a(ch + 2, ch & 1, t, i32, j0, sb);
            g2_fill_w(ch + 2, ch & 1, t, sb);
            CP_COMMIT();
        }
    }

    // ---- epilogue: + bo, / norm, store float2 -----------------------------
    int gid = lane >> 2, ctid = lane & 3;
#pragma unroll
    for (int mi = 0; mi < 2; mi++) {
#pragma unroll
        for (int rr = 0; rr < 2; rr++) {
            int rl = wm * 32 + mi * 16 + gid + rr * 8;
            int mrow = i * N_DIM + j0 + rl;
            float inv = 1.f / g_norm[mrow];
#pragma unroll
            for (int ni = 0; ni < 4; ni++) {
                int z = wn * 32 + ni * 8 + 2 * ctid;
                float2 o;
                o.x = (C[mi][ni][rr * 2 + 0] + bo[z])     * inv;
                o.y = (C[mi][ni][rr * 2 + 1] + bo[z + 1]) * inv;
                *(float2*)(out + (size_t)mrow * CZ + z) = o;
            }
        }
    }
}

// ---------------------------------------------------------------------------
extern "C" void kernel_launch(void* const* d_in, const int* in_sizes, int n_in,
                              void* d_out, int out_size)
{
    const float* m    = (const float*)d_in[0];
    const float* mask = (const float*)d_in[1];
    const float* ln_w = (const float*)d_in[2];
    const float* ln_b = (const float*)d_in[3];
    const float* w1   = (const float*)d_in[4];
    const float* b1   = (const float*)d_in[5];
    const float* w2   = (const float*)d_in[6];
    const float* b2   = (const float*)d_in[7];
    const float* wo   = (const float*)d_in[8];
    const float* bo   = (const float*)d_in[9];
    float* out = (float*)d_out;
    (void)in_sizes; (void)n_in; (void)out_size;

    cudaFuncSetAttribute(gemm1_kernel, cudaFuncAttributeMaxDynamicSharedMemorySize, SM1);
    cudaFuncSetAttribute(gemm2_kernel, cudaFuncAttributeMaxDynamicSharedMemorySize, SM2);

    ln_proj_kernel<<<S_DIM * (N_DIM / 8), 256>>>(m, mask, ln_w, ln_b, w1, b1, w2, b2);
    wot_kernel<<<512, 256>>>(wo);
    norm_kernel<<<N_DIM, N_DIM>>>(mask);
    gemm1_kernel<<<dim3(64, 64), 512, SM1>>>();
    gemm2_kernel<<<512, 512, SM2>>>(bo, out);
}

// round 14
// speedup vs baseline: 1.0956x; 1.0956x over previous
#include <cuda_runtime.h>
#include <cuda_bf16.h>
#include <cstdint>

#define S_DIM 128
#define N_DIM 256
#define CM    256
#define CH    32
#define CZ    128
#define KCD   (CH*CH)            // 1024
#define MPAIRS (N_DIM*N_DIM)     // 65536
#define NC    (N_DIM*CH)         // 8192

// ---------------- device scratch ------------------------------------------
__device__ __align__(16) unsigned short g_ah[S_DIM * NC];  // a hi bf16 [s][n*32+c]
__device__ __align__(16) unsigned short g_al[S_DIM * NC];  // a lo
__device__ __align__(16) unsigned short g_bh[S_DIM * NC];  // b hi
__device__ __align__(16) unsigned short g_bl[S_DIM * NC];  // b lo
__device__ __align__(16) unsigned short g_qh[(size_t)NC * NC]; // Q hi bf16 [i*32+c][j*32+d]
__device__ __align__(16) unsigned short g_ql[(size_t)NC * NC]; // Q lo bf16
__device__ __align__(16) unsigned short g_wth[CZ * KCD]; // woT hi bf16 [z][cd]
__device__ __align__(16) unsigned short g_wtl[CZ * KCD]; // woT lo bf16
__device__ float g_norm[MPAIRS];                         // norm + eps

// ---------------- helpers ---------------------------------------------------
__device__ __forceinline__ uint32_t smem_u32(const void* p) {
    uint32_t a;
    asm("{ .reg .u64 t; cvta.to.shared.u64 t, %1; cvt.u32.u64 %0, t; }"
        : "=r"(a) : "l"(p));
    return a;
}
__device__ __forceinline__ void split_bf16(float v, unsigned short& h, unsigned short& l) {
    __nv_bfloat16 hb = __float2bfloat16(v);
    __nv_bfloat16 lb = __float2bfloat16(v - __bfloat162float(hb));
    h = __bfloat16_as_ushort(hb);
    l = __bfloat16_as_ushort(lb);
}
__device__ __forceinline__ void ldsm_x4(uint32_t* r, uint32_t a) {
    asm volatile("ldmatrix.sync.aligned.m8n8.x4.shared.b16 {%0,%1,%2,%3}, [%4];"
        : "=r"(r[0]), "=r"(r[1]), "=r"(r[2]), "=r"(r[3]) : "r"(a));
}
__device__ __forceinline__ void ldsm_x4_t(uint32_t* r, uint32_t a) {
    asm volatile("ldmatrix.sync.aligned.m8n8.x4.trans.shared.b16 {%0,%1,%2,%3}, [%4];"
        : "=r"(r[0]), "=r"(r[1]), "=r"(r[2]), "=r"(r[3]) : "r"(a));
}
__device__ __forceinline__ void mma16816(float* c, const uint32_t* a, const uint32_t* b) {
    asm volatile("mma.sync.aligned.m16n8k16.row.col.f32.bf16.bf16.f32 "
        "{%0,%1,%2,%3}, {%4,%5,%6,%7}, {%8,%9}, {%0,%1,%2,%3};"
        : "+f"(c[0]), "+f"(c[1]), "+f"(c[2]), "+f"(c[3])
        : "r"(a[0]), "r"(a[1]), "r"(a[2]), "r"(a[3]), "r"(b[0]), "r"(b[1]));
}
#define CP_ASYNC16(dst, src) \
    asm volatile("cp.async.cg.shared.global [%0], [%1], 16;" \
                 :: "r"(dst), "l"(src) : "memory")
#define CP_COMMIT()  asm volatile("cp.async.commit_group;" ::: "memory")
#define CP_WAIT(n)   asm volatile("cp.async.wait_group %0;" :: "n"(n) : "memory")

// ---------------------------------------------------------------------------
// Kernel A: LayerNorm + two projections + hi/lo bf16 split (proven)
// ---------------------------------------------------------------------------
__global__ void __launch_bounds__(256) ln_proj_kernel(
    const float* __restrict__ m, const float* __restrict__ mask,
    const float* __restrict__ ln_w, const float* __restrict__ ln_b,
    const float* __restrict__ w1, const float* __restrict__ b1,
    const float* __restrict__ w2, const float* __restrict__ b2)
{
    __shared__ float lnsm[8][CM];
    __shared__ float pa[4][8][CH];
    __shared__ float pb[4][8][CH];
    __shared__ float masksm[8];

    int t = threadIdx.x, warp = t >> 5, lane = t & 31;
    int bid = blockIdx.x;
    int s = bid >> 5, n0 = (bid & 31) << 3;

    {
        int r = warp;
        const float* row = m + ((size_t)s * N_DIM + n0 + r) * CM;
        float v[8], sum = 0.f, sq = 0.f;
#pragma unroll
        for (int x = 0; x < 8; x++) { v[x] = row[lane + 32 * x]; sum += v[x]; sq += v[x] * v[x]; }
#pragma unroll
        for (int o = 16; o > 0; o >>= 1) {
            sum += __shfl_xor_sync(0xffffffffu, sum, o);
            sq  += __shfl_xor_sync(0xffffffffu, sq, o);
        }
        float mu = sum * (1.f / CM);
        float inv = rsqrtf(sq * (1.f / CM) - mu * mu + 1e-5f);
#pragma unroll
        for (int x = 0; x < 8; x++) {
            int k = lane + 32 * x;
            lnsm[r][k] = (v[x] - mu) * inv * ln_w[k] + ln_b[k];
        }
        if (lane == 0) masksm[r] = mask[s * N_DIM + n0 + r];
    }
    __syncthreads();
    {
        const float* W = (warp < 4) ? w1 : w2;
        int wq = warp & 3;
        float acc[8];
#pragma unroll
        for (int r = 0; r < 8; r++) acc[r] = 0.f;
        int kbeg = wq * 64;
#pragma unroll 8
        for (int k = kbeg; k < kbeg + 64; k++) {
            float wv = W[k * CH + lane];
#pragma unroll
            for (int r = 0; r < 8; r++) acc[r] += lnsm[r][k] * wv;
        }
        if (warp < 4) {
#pragma unroll
            for (int r = 0; r < 8; r++) pa[wq][r][lane] = acc[r];
        } else {
#pragma unroll
            for (int r = 0; r < 8; r++) pb[wq][r][lane] = acc[r];
        }
    }
    __syncthreads();
    {
        int r = t >> 5, c = t & 31;
        float av = pa[0][r][c] + pa[1][r][c] + pa[2][r][c] + pa[3][r][c] + b1[c];
        float bv = pb[0][r][c] + pb[1][r][c] + pb[2][r][c] + pb[3][r][c] + b2[c];
        float mv = masksm[r];
        size_t off = ((size_t)s * N_DIM + n0 + r) * CH + c;
        unsigned short h, l;
        split_bf16(av * mv, h, l);
        g_ah[off] = h;  g_al[off] = l;
        split_bf16(bv * mv, h, l);
        g_bh[off] = h;  g_bl[off] = l;
    }
}

// woT: transpose + hi/lo split of wo  ([cd][z] -> [z][cd])
__global__ void __launch_bounds__(256) wot_kernel(const float* __restrict__ wo)
{
    int idx = blockIdx.x * 256 + threadIdx.x;
    int z = idx >> 10, cd = idx & 1023;
    unsigned short h, l;
    split_bf16(wo[cd * CZ + z], h, l);
    g_wth[z * KCD + cd] = h;
    g_wtl[z * KCD + cd] = l;
}

// norm[i,j] = sum_s mask[s,i]*mask[s,j] + eps
__global__ void __launch_bounds__(256) norm_kernel(const float* __restrict__ mask)
{
    int i = blockIdx.x, j = threadIdx.x;
    float acc = 0.f;
#pragma unroll 8
    for (int s = 0; s < S_DIM; s++)
        acc += mask[s * N_DIM + i] * mask[s * N_DIM + j];
    g_norm[i * N_DIM + j] = acc + 1e-3f;
}

// ---------------------------------------------------------------------------
// GEMM1: Q = a^T b  (8192x8192, K=128), 3-pass bf16 mma.
// 512 threads, warp tile 32x32, cp.async fill, double-buffered.
// NEW: fragments loaded ONCE per k-step, shared across the 3 passes
// (12 -> 8 ldsm_x4 per warp per k-step).
// ---------------------------------------------------------------------------
#define LDM1   136
#define LDM1B  (LDM1*2)          // 272
#define PL1    (64 * LDM1B)      // 17408 per plane
#define STG1   (4 * PL1)         // 69632 per stage
#define SM1    (2 * STG1)        // 139264

__device__ __forceinline__ void g1_fill(int ch, int sg, int t, int m0, int n0,
                                        uint32_t sb)
{
#pragma unroll
    for (int it = 0; it < 2; it++) {
        int vi = it * 512 + t;                  // 0..1023 chunks per plane
        int sl = vi >> 4, q = vi & 15;
        size_t sra = (size_t)(ch * 64 + sl) * NC + m0 + q * 8;
        size_t srb = (size_t)(ch * 64 + sl) * NC + n0 + q * 8;
        uint32_t dst = sb + (uint32_t)sg * STG1 + (uint32_t)(sl * LDM1B + q * 16);
        CP_ASYNC16(dst,            g_ah + sra);
        CP_ASYNC16(dst + PL1,      g_al + sra);
        CP_ASYNC16(dst + 2 * PL1,  g_bh + srb);
        CP_ASYNC16(dst + 3 * PL1,  g_bl + srb);
    }
}

__global__ void __launch_bounds__(512) gemm1_kernel()
{
    extern __shared__ unsigned char sm1[];
    const uint32_t sb = smem_u32(sm1);

    int t = threadIdx.x, w = t >> 5, lane = t & 31;
    int wm = w >> 2, wn = w & 3;                // 4x4 warps, tile 32x32
    int m0 = blockIdx.x * 128, n0 = blockIdx.y * 128;

    float C[2][4][4];
#pragma unroll
    for (int mi = 0; mi < 2; mi++)
#pragma unroll
        for (int ni = 0; ni < 4; ni++)
#pragma unroll
            for (int e = 0; e < 4; e++) C[mi][ni][e] = 0.f;

    g1_fill(0, 0, t, m0, n0, sb);
    CP_COMMIT();
    g1_fill(1, 1, t, m0, n0, sb);
    CP_COMMIT();

    for (int ch = 0; ch < 2; ch++) {
        if (ch == 0) { CP_WAIT(1); } else { CP_WAIT(0); }
        __syncthreads();

        uint32_t Sb = sb + (uint32_t)(ch & 1) * STG1;
        uint32_t AHp = Sb, ALp = Sb + PL1, BHp = Sb + 2 * PL1, BLp = Sb + 3 * PL1;
#pragma unroll
        for (int ks = 0; ks < 4; ks++) {
            int kb = ks * 16;
            // per-fragment smem offsets (k-step dependent)
            uint32_t aoff[2], boff[2];
#pragma unroll
            for (int mi = 0; mi < 2; mi++) {
                int mb = wm * 32 + mi * 16;
                aoff[mi] = (uint32_t)(kb + ((lane >> 4) & 1) * 8 + (lane & 7)) * LDM1B
                         + (uint32_t)(mb + (lane & 8)) * 2;
            }
#pragma unroll
            for (int np = 0; np < 2; np++) {
                int nb = wn * 32 + np * 16;
                boff[np] = (uint32_t)(kb + ((lane >> 3) & 1) * 8 + (lane & 7)) * LDM1B
                         + (uint32_t)(nb + (lane >> 4) * 8) * 2;
            }
            // load B hi/lo once
            uint32_t bh[4][2], bl[4][2];
#pragma unroll
            for (int np = 0; np < 2; np++) {
                uint32_t r4[4];
                ldsm_x4_t(r4, BHp + boff[np]);
                bh[2 * np][0] = r4[0]; bh[2 * np][1] = r4[1];
                bh[2 * np + 1][0] = r4[2]; bh[2 * np + 1][1] = r4[3];
                ldsm_x4_t(r4, BLp + boff[np]);
                bl[2 * np][0] = r4[0]; bl[2 * np][1] = r4[1];
                bl[2 * np + 1][0] = r4[2]; bl[2 * np + 1][1] = r4[3];
            }
            // A hi: passes ah*bh and ah*bl
            uint32_t af[2][4];
#pragma unroll
            for (int mi = 0; mi < 2; mi++) ldsm_x4_t(af[mi], AHp + aoff[mi]);
#pragma unroll
            for (int mi = 0; mi < 2; mi++)
#pragma unroll
                for (int ni = 0; ni < 4; ni++) {
                    mma16816(C[mi][ni], af[mi], bh[ni]);
                    mma16816(C[mi][ni], af[mi], bl[ni]);
                }
            // A lo: pass al*bh
#pragma unroll
            for (int mi = 0; mi < 2; mi++) ldsm_x4_t(af[mi], ALp + aoff[mi]);
#pragma unroll
            for (int mi = 0; mi < 2; mi++)
#pragma unroll
                for (int ni = 0; ni < 4; ni++)
                    mma16816(C[mi][ni], af[mi], bh[ni]);
        }
    }

    // ---- epilogue: stage C (hi/lo) in stage-0 smem, then coalesced STG ----
    {
        unsigned short* Eh = (unsigned short*)(sm1);            // [128][136]
        unsigned short* El = (unsigned short*)(sm1 + 2 * PL1);  // [128][136]
        int gid = lane >> 2, ctid = lane & 3;
#pragma unroll
        for (int mi = 0; mi < 2; mi++) {
#pragma unroll
            for (int rr = 0; rr < 2; rr++) {
                int r = wm * 32 + mi * 16 + gid + rr * 8;
#pragma unroll
                for (int ni = 0; ni < 4; ni++) {
                    int col = wn * 32 + ni * 8 + 2 * ctid;
                    unsigned short h0, l0, h1, l1;
                    split_bf16(C[mi][ni][rr * 2 + 0], h0, l0);
                    split_bf16(C[mi][ni][rr * 2 + 1], h1, l1);
                    *(uint32_t*)(Eh + r * LDM1 + col) = ((uint32_t)h1 << 16) | h0;
                    *(uint32_t*)(El + r * LDM1 + col) = ((uint32_t)l1 << 16) | l0;
                }
            }
        }
        __syncthreads();
#pragma unroll
        for (int it = 0; it < 4; it++) {
            int vi = it * 512 + t;                   // 0..2047
            int r = vi >> 4, q = vi & 15;
            uint4 vh = *(const uint4*)(sm1 + (uint32_t)(r * LDM1B + q * 16));
            uint4 vl = *(const uint4*)(sm1 + 2 * PL1 + (uint32_t)(r * LDM1B + q * 16));
            size_t dst = (size_t)(m0 + r) * NC + n0 + q * 8;
            *(uint4*)(g_qh + dst) = vh;
            *(uint4*)(g_ql + dst) = vl;
        }
    }
}

// ---------------------------------------------------------------------------
// GEMM2: out = Q @ woT  (M=65536, N=128, K=1024), 3-pass, double-buffered.
// 256 threads (round-12 proven), 4x2 warp grid, 32x64 warp tile.
// NEW: fragments loaded ONCE per k-step (18 -> 12 ldsm per warp per k-step).
// ---------------------------------------------------------------------------
#define LDK2   72
#define LDK2B  (LDK2*2)          // 144
#define APL    (128 * LDK2B)     // 18432
#define ASTG   (2 * APL)         // 36864 per stage
#define OFF_W  (2 * ASTG)        // 73728
#define SM2    (OFF_W + 2 * ASTG) // 147456

__device__ __forceinline__ void g2_fill_a(int ch, int sg, int t, int i32, int j0,
                                          uint32_t sb)
{
#pragma unroll
    for (int it = 0; it < 4; it++) {
        int vi = it * 256 + t;
        int cl = vi >> 9, rem = vi & 511;
        int jl = rem >> 2, q = rem & 3;
        size_t src = (size_t)(i32 + 2 * ch + cl) * NC + (size_t)(j0 + jl) * 32 + q * 8;
        uint32_t dst = sb + (uint32_t)sg * ASTG + (uint32_t)(jl * LDK2B + cl * 64 + q * 16);
        CP_ASYNC16(dst, g_qh + src);
        CP_ASYNC16(dst + APL, g_ql + src);
    }
}
__device__ __forceinline__ void g2_fill_w(int ch, int sg, int t, uint32_t sb)
{
#pragma unroll
    for (int it = 0; it < 4; it++) {
        int vi = it * 256 + t;
        int r = vi >> 3, q = vi & 7;
        size_t src = (size_t)r * KCD + ch * 64 + q * 8;
        uint32_t dst = sb + OFF_W + (uint32_t)sg * ASTG + (uint32_t)(r * LDK2B + q * 16);
        CP_ASYNC16(dst, g_wth + src);
        CP_ASYNC16(dst + APL, g_wtl + src);
    }
}

__global__ void __launch_bounds__(256) gemm2_kernel(
    const float* __restrict__ bo, float* __restrict__ out)
{
    extern __shared__ unsigned char sm2[];
    const uint32_t sb = smem_u32(sm2);

    int t = threadIdx.x, w = t >> 5, lane = t & 31;
    int wm = w >> 1, wn = w & 1;
    int i = blockIdx.x >> 1;
    int j0 = (blockIdx.x & 1) * 128;
    int i32 = i * 32;

    float C[2][8][4];
#pragma unroll
    for (int mi = 0; mi < 2; mi++)
#pragma unroll
        for (int ni = 0; ni < 8; ni++)
#pragma unroll
            for (int e = 0; e < 4; e++) C[mi][ni][e] = 0.f;

    g2_fill_a(0, 0, t, i32, j0, sb);
    g2_fill_w(0, 0, t, sb);
    CP_COMMIT();
    g2_fill_a(1, 1, t, i32, j0, sb);
    g2_fill_w(1, 1, t, sb);
    CP_COMMIT();

    for (int ch = 0; ch < 16; ch++) {
        if (ch < 15) { CP_WAIT(1); } else { CP_WAIT(0); }
        __syncthreads();

        uint32_t Abase = sb + (uint32_t)(ch & 1) * ASTG;
        uint32_t Wbase = sb + OFF_W + (uint32_t)(ch & 1) * ASTG;
        uint32_t AHp = Abase, ALp = Abase + APL, WHp = Wbase, WLp = Wbase + APL;
#pragma unroll
        for (int ks = 0; ks < 4; ks++) {
            int kb = ks * 16;
            uint32_t aoff[2], boff[4];
#pragma unroll
            for (int mi = 0; mi < 2; mi++) {
                int mb = wm * 32 + mi * 16;
                aoff[mi] = (uint32_t)(mb + (lane & 15)) * LDK2B
                         + (uint32_t)(kb + (lane >> 4) * 8) * 2;
            }
#pragma unroll
            for (int np = 0; np < 4; np++) {
                int nb = wn * 64 + np * 16;
                boff[np] = (uint32_t)(nb + (lane >> 4) * 8 + (lane & 7)) * LDK2B
                         + (uint32_t)(kb + ((lane >> 3) & 1) * 8) * 2;
            }
            // W hi/lo fragments once
            uint32_t bh[8][2], bl[8][2];
#pragma unroll
            for (int np = 0; np < 4; np++) {
                uint32_t r4[4];
                ldsm_x4(r4, WHp + boff[np]);
                bh[2 * np][0] = r4[0]; bh[2 * np][1] = r4[1];
                bh[2 * np + 1][0] = r4[2]; bh[2 * np + 1][1] = r4[3];
                ldsm_x4(r4, WLp + boff[np]);
                bl[2 * np][0] = r4[0]; bl[2 * np][1] = r4[1];
                bl[2 * np + 1][0] = r4[2]; bl[2 * np + 1][1] = r4[3];
            }
            // Q hi: qh*wh and qh*wl
            uint32_t af[2][4];
#pragma unroll
            for (int mi = 0; mi < 2; mi++) ldsm_x4(af[mi], AHp + aoff[mi]);
#pragma unroll
            for (int mi = 0; mi < 2; mi++)
#pragma unroll
                for (int ni = 0; ni < 8; ni++) {
                    mma16816(C[mi][ni], af[mi], bh[ni]);
                    mma16816(C[mi][ni], af[mi], bl[ni]);
                }
            // Q lo: ql*wh
#pragma unroll
            for (int mi = 0; mi < 2; mi++) ldsm_x4(af[mi], ALp + aoff[mi]);
#pragma unroll
            for (int mi = 0; mi < 2; mi++)
#pragma unroll
                for (int ni = 0; ni < 8; ni++)
                    mma16816(C[mi][ni], af[mi], bh[ni]);
        }
        __syncthreads();
        if (ch + 2 < 16) {
            g2_fill_a(ch + 2, ch & 1, t, i32, j0, sb);
            g2_fill_w(ch + 2, ch & 1, t, sb);
            CP_COMMIT();
        }
    }

    // ---- epilogue: + bo, / norm, store float2 -----------------------------
    int gid = lane >> 2, ctid = lane & 3;
#pragma unroll
    for (int mi = 0; mi < 2; mi++) {
#pragma unroll
        for (int rr = 0; rr < 2; rr++) {
            int rl = wm * 32 + mi * 16 + gid + rr * 8;
            int mrow = i * N_DIM + j0 + rl;
            float inv = 1.f / g_norm[mrow];
#pragma unroll
            for (int ni = 0; ni < 8; ni++) {
                int z = wn * 64 + ni * 8 + 2 * ctid;
                float2 o;
                o.x = (C[mi][ni][rr * 2 + 0] + bo[z])     * inv;
                o.y = (C[mi][ni][rr * 2 + 1] + bo[z + 1]) * inv;
                *(float2*)(out + (size_t)mrow * CZ + z) = o;
            }
        }
    }
}

// ---------------------------------------------------------------------------
extern "C" void kernel_launch(void* const* d_in, const int* in_sizes, int n_in,
                              void* d_out, int out_size)
{
    const float* m    = (const float*)d_in[0];
    const float* mask = (const float*)d_in[1];
    const float* ln_w = (const float*)d_in[2];
    const float* ln_b = (const float*)d_in[3];
    const float* w1   = (const float*)d_in[4];
    const float* b1   = (const float*)d_in[5];
    const float* w2   = (const float*)d_in[6];
    const float* b2   = (const float*)d_in[7];
    const float* wo   = (const float*)d_in[8];
    const float* bo   = (const float*)d_in[9];
    float* out = (float*)d_out;
    (void)in_sizes; (void)n_in; (void)out_size;

    cudaFuncSetAttribute(gemm1_kernel, cudaFuncAttributeMaxDynamicSharedMemorySize, SM1);
    cudaFuncSetAttribute(gemm2_kernel, cudaFuncAttributeMaxDynamicSharedMemorySize, SM2);

    ln_proj_kernel<<<S_DIM * (N_DIM / 8), 256>>>(m, mask, ln_w, ln_b, w1, b1, w2, b2);
    wot_kernel<<<512, 256>>>(wo);
    norm_kernel<<<N_DIM, N_DIM>>>(mask);
    gemm1_kernel<<<dim3(64, 64), 512, SM1>>>();
    gemm2_kernel<<<512, 256, SM2>>>(bo, out);
}